// round 7
// baseline (speedup 1.0000x reference)
#include <cuda_runtime.h>
#include <cuda_fp16.h>
#include <cstdint>

// ============================================================================
// Problem constants
// ============================================================================
#define D_IN   1024
#define D_OUT  2048
#define NROWS  8192               // 4 * 2048
#define KBAS   8192               // basis block: k = d*8 + j
#define KTOT   9216               // + silu block: k = 8192 + d
#define BM     128
#define BN     128
#define BK     64                 // 64 fp16 = 128B rows = SW128 atom
#define NSTEPS (KTOT / BK)        // 144  (multiple of NSTAGES -> cross-tile flow)
#define NSTAGES 6
#define NTILES ((NROWS / BM) * (D_OUT / BN))   // 1024
#define GRIDP  148                              // persistent CTAs
#define MAXT   7                                // max tiles per CTA

// SMEM: 6 stages, each = A(16KB) + B(16KB) = 32KB
#define SM_STAGE   32768
#define SMEM_TOTAL (NSTAGES * SM_STAGE)         // 196608

// ============================================================================
// Device scratch (static __device__ arrays: sanctioned no-alloc workaround)
// ============================================================================
__device__ __half g_A[(size_t)NROWS * KTOT];   // 151 MB
__device__ __half g_W[(size_t)D_OUT * KTOT];   // 37.7 MB

// ============================================================================
// PTX helpers (base ISA only — harness builds for compute_103, no 'a')
// ============================================================================
__device__ __forceinline__ uint32_t smem_u32(const void* p) {
    uint32_t a;
    asm("{ .reg .u64 t; cvta.to.shared.u64 t, %1; cvt.u32.u64 %0, t; }" : "=r"(a) : "l"(p));
    return a;
}

__device__ __forceinline__ void cp16(uint32_t dst, const void* src) {
    asm volatile("cp.async.cg.shared.global [%0], [%1], 16;" :: "r"(dst), "l"(src));
}
#define CP_COMMIT() asm volatile("cp.async.commit_group;" ::: "memory")
#define CP_WAIT_4() asm volatile("cp.async.wait_group 4;" ::: "memory")

__device__ __forceinline__ void ldsm_x4(uint32_t* r, uint32_t addr) {
    asm volatile("ldmatrix.sync.aligned.m8n8.x4.shared.b16 {%0,%1,%2,%3}, [%4];"
                 : "=r"(r[0]), "=r"(r[1]), "=r"(r[2]), "=r"(r[3]) : "r"(addr));
}

__device__ __forceinline__ void mma_f16(float* c, const uint32_t* a,
                                        uint32_t b0, uint32_t b1) {
    asm volatile(
        "mma.sync.aligned.m16n8k16.row.col.f32.f16.f16.f32 "
        "{%0,%1,%2,%3}, {%4,%5,%6,%7}, {%8,%9}, {%0,%1,%2,%3};"
        : "+f"(c[0]), "+f"(c[1]), "+f"(c[2]), "+f"(c[3])
        : "r"(a[0]), "r"(a[1]), "r"(a[2]), "r"(a[3]), "r"(b0), "r"(b1));
}

// ============================================================================
// Merged prep kernel. Blocks [0, 32768): A-side (one thread per (n,d)):
//   basis block A[n][d*8+j] = B_j(x[n,d]) (exact Cox-de-Boor recursion,
//   uniform-grid: all denominators are p*h -> one rcp, zero divides);
//   silu block  A[n][8192+d] = silu(x[n,d]).
// Blocks [32768, 40960): W-side (one thread per (d,o)):
//   W[o][d*8+j] = coef[d][o][j]*ssp[d][o];  W[o][8192+d] = sb[d][o].
// ============================================================================
__global__ void prep_kernel(const float* __restrict__ x, const float* __restrict__ grid,
                            const float* __restrict__ coef, const float* __restrict__ sb,
                            const float* __restrict__ ssp) {
    if (blockIdx.x < 32768u) {
        int idx = blockIdx.x * blockDim.x + threadIdx.x;   // n*1024 + d
        int d = idx & (D_IN - 1);
        int n = idx >> 10;
        float xv = x[idx];
        float gv[12];
#pragma unroll
        for (int m = 0; m < 12; m++) gv[m] = __ldg(grid + d * 12 + m);

        const float invh  = __frcp_rn(gv[1] - gv[0]);
        const float invp[3] = {invh, 0.5f * invh, (1.0f / 3.0f) * invh};

        float B[11];
#pragma unroll
        for (int m = 0; m < 11; m++)
            B[m] = (xv >= gv[m] && xv < gv[m + 1]) ? 1.0f : 0.0f;
#pragma unroll
        for (int p = 1; p <= 3; p++) {
            const float ip = invp[p - 1];
#pragma unroll
            for (int m = 0; m < 11 - p; m++) {
                float left  = (xv - gv[m]) * ip;
                float right = (gv[m + p + 1] - xv) * ip;
                B[m] = left * B[m] + right * B[m + 1];
            }
        }
        __half2 h[4];
#pragma unroll
        for (int j = 0; j < 4; j++)
            h[j] = __floats2half2_rn(B[2 * j], B[2 * j + 1]);
        *reinterpret_cast<uint4*>(g_A + (size_t)n * KTOT + d * 8) =
            *reinterpret_cast<uint4*>(h);
        float s = xv * __frcp_rn(1.0f + __expf(-xv));
        g_A[(size_t)n * KTOT + KBAS + d] = __float2half_rn(s);
    } else {
        int idx = (blockIdx.x - 32768u) * blockDim.x + threadIdx.x;  // d*2048 + o
        int o = idx & (D_OUT - 1);
        int d = idx >> 11;
        size_t doo = (size_t)d * D_OUT + o;
        float ss = ssp[doo];
        float4 c0 = *reinterpret_cast<const float4*>(coef + doo * 8);
        float4 c1 = *reinterpret_cast<const float4*>(coef + doo * 8 + 4);
        __half2 h[4];
        h[0] = __floats2half2_rn(c0.x * ss, c0.y * ss);
        h[1] = __floats2half2_rn(c0.z * ss, c0.w * ss);
        h[2] = __floats2half2_rn(c1.x * ss, c1.y * ss);
        h[3] = __floats2half2_rn(c1.z * ss, c1.w * ss);
        *reinterpret_cast<uint4*>(g_W + (size_t)o * KTOT + d * 8) =
            *reinterpret_cast<uint4*>(h);
        g_W[(size_t)o * KTOT + KBAS + d] = __float2half_rn(sb[doo]);
    }
}

// ============================================================================
// Persistent GEMM: out[8192,2048] = A @ W^T  (fp16 m16n8k16, f32 acc)
// 148 CTAs x 256 thr (8 warps 2x4, warp tile 64x32). 1024 tiles of 128x128,
// strided assignment (concurrent CTAs stay in a contiguous 148-tile window ->
// L2-resident working set). 6-stage cp.async pipeline flows across tile
// boundaries (NSTEPS % NSTAGES == 0) -> no re-prologue, epilogue overlapped.
// ============================================================================
__global__ __launch_bounds__(256, 1)
void kan_gemm_kernel(float* __restrict__ out) {
    extern __shared__ __align__(128) char smem[];
    const uint32_t sbase = smem_u32(smem);
    const int tid  = threadIdx.x;
    const int lane = tid & 31;
    const int wid  = tid >> 5;          // 0..7
    const int wm   = wid & 1;           // 2 m-bands of 64
    const int wn   = wid >> 1;          // 4 n-bands of 32

    // ---- persistent tile list (strided: wavefront stays contiguous) ----
    int myTiles[MAXT], nt = 0;
    for (int t = blockIdx.x; t < NTILES; t += GRIDP) myTiles[nt++] = t;
    if (nt == 0) return;
    const int TOT = nt * NSTEPS;

    // ---- fill: A 128 rows x 8 units + B 128 rows x 8 units (16B units) ----
    const int fr = tid >> 3;            // base row 0..31
    const int fu = tid & 7;             // unit within 128B row
    const int fsw = (fu ^ (fr & 7)) << 4;
    auto fill = [&](int s, int tile, int k) {
        const int m0 = (tile >> 4) * BM;
        const int n0 = (tile & 15) * BN;
        const __half* Asrc = g_A + (size_t)(m0 + fr) * KTOT + (size_t)k * BK + fu * 8;
        const __half* Bsrc = g_W + (size_t)(n0 + fr) * KTOT + (size_t)k * BK + fu * 8;
        uint32_t sA = sbase + s * SM_STAGE + fr * 128 + fsw;
        uint32_t sB = sA + 16384;
#pragma unroll
        for (int i = 0; i < 4; i++)
            cp16(sA + i * 32 * 128, Asrc + (size_t)i * 32 * KTOT);
#pragma unroll
        for (int i = 0; i < 4; i++)
            cp16(sB + i * 32 * 128, Bsrc + (size_t)i * 32 * KTOT);
    };

    // Prologue: global steps 0..4 (all inside tile 0: NSTEPS=144 > 5)
#pragma unroll
    for (int s = 0; s < NSTAGES - 1; s++) {
        fill(s, myTiles[0], s);
        CP_COMMIT();
    }

    float acc[4][4][4];
#pragma unroll
    for (int a = 0; a < 4; a++)
#pragma unroll
        for (int j = 0; j < 4; j++)
#pragma unroll
            for (int c = 0; c < 4; c++) acc[a][j][c] = 0.0f;

    // ldmatrix addressing (x4 = one 16x16 fp16 tile)
    const int s7  = lane & 7;
    const int hi  = lane >> 4;
    const int r16 = lane & 15;
    const uint32_t rowA_off = (uint32_t)(wm * 64 + r16) * 128;
    const uint32_t rowB_off = (uint32_t)(wn * 32 + r16) * 128 + 16384;

    int k = 0, ti = 0;                  // consume position
    int kf = NSTAGES - 1, tif = 0;      // fill-ahead position

    for (int gk = 0; gk < TOT; gk++) {
        const int s = gk % NSTAGES;
        CP_WAIT_4();                    // stage s resident
        __syncthreads();                // all warps done reading retiring stage

        if (gk + NSTAGES - 1 < TOT)
            fill((gk + NSTAGES - 1) % NSTAGES, myTiles[tif], kf);
        CP_COMMIT();                    // empty group in tail keeps count exact
        if (++kf == NSTEPS) { kf = 0; tif++; }

        const uint32_t sA = sbase + s * SM_STAGE + rowA_off;
        const uint32_t sB = sbase + s * SM_STAGE + rowB_off;
#pragma unroll
        for (int kc = 0; kc < 4; kc++) {
            const uint32_t u = ((uint32_t)((kc * 2 + hi) ^ s7)) << 4;
            uint32_t af[4][4], bf[2][4];
#pragma unroll
            for (int a = 0; a < 4; a++) ldsm_x4(af[a], sA + a * 16 * 128 + u);
#pragma unroll
            for (int nb = 0; nb < 2; nb++) ldsm_x4(bf[nb], sB + nb * 16 * 128 + u);
#pragma unroll
            for (int a = 0; a < 4; a++)
#pragma unroll
                for (int nb = 0; nb < 2; nb++) {
                    mma_f16(acc[a][nb * 2 + 0], af[a], bf[nb][0], bf[nb][2]);
                    mma_f16(acc[a][nb * 2 + 1], af[a], bf[nb][1], bf[nb][3]);
                }
        }

        if (++k == NSTEPS) {            // tile done: epilogue (regs->gmem) + reset
            k = 0;
            const int tile = myTiles[ti++];
            const int m0 = (tile >> 4) * BM;
            const int n0 = (tile & 15) * BN;
            const int orow0 = m0 + wm * 64 + (lane >> 2);
            const int ocol0 = n0 + wn * 32 + (lane & 3) * 2;
#pragma unroll
            for (int a = 0; a < 4; a++) {
                float* p0 = out + (size_t)(orow0 + a * 16) * D_OUT + ocol0;
                float* p1 = p0 + 8 * D_OUT;
#pragma unroll
                for (int j = 0; j < 4; j++) {
                    *reinterpret_cast<float2*>(p0 + j * 8) =
                        make_float2(acc[a][j][0], acc[a][j][1]);
                    *reinterpret_cast<float2*>(p1 + j * 8) =
                        make_float2(acc[a][j][2], acc[a][j][3]);
                    acc[a][j][0] = acc[a][j][1] = acc[a][j][2] = acc[a][j][3] = 0.0f;
                }
            }
        }
    }
}

// ============================================================================
// Host launch (graph-capturable: kernel launches only)
// ============================================================================
extern "C" void kernel_launch(void* const* d_in, const int* in_sizes, int n_in,
                              void* d_out, int out_size) {
    const float* x    = (const float*)d_in[0];   // (4,2048,1024)
    const float* grid = (const float*)d_in[1];   // (1024,12)
    const float* coef = (const float*)d_in[2];   // (1024,2048,8)
    const float* sb   = (const float*)d_in[3];   // (1024,2048)
    const float* ssp  = (const float*)d_in[4];   // (1024,2048)
    float* out = (float*)d_out;                  // (4,2048,2048)

    prep_kernel<<<32768 + 8192, 256>>>(x, grid, coef, sb, ssp);

    cudaFuncSetAttribute(kan_gemm_kernel,
                         cudaFuncAttributeMaxDynamicSharedMemorySize, SMEM_TOTAL);
    kan_gemm_kernel<<<GRIDP, 256, SMEM_TOTAL>>>(out);
}

// round 9
// speedup vs baseline: 1.1834x; 1.1834x over previous
#include <cuda_runtime.h>
#include <cuda_fp16.h>
#include <cstdint>

// ============================================================================
// Problem constants
// ============================================================================
#define D_IN   1024
#define D_OUT  2048
#define NROWS  8192               // 4 * 2048
#define KBAS   8192               // basis block: k = d*8 + j
#define KTOT   9216               // + silu block: k = 8192 + d
#define BM     128
#define BN     128
#define BK     64                 // 64 fp16 = 128B rows = SW128 atom
#define NSTEPS (KTOT / BK)        // 144
#define NSTAGES 3

// SMEM: 3 stages, each = A(16KB) + B(16KB) = 32KB -> 96KB => 2 CTAs/SM
#define SM_STAGE   32768
#define SMEM_TOTAL (NSTAGES * SM_STAGE)         // 98304

// ============================================================================
// Device scratch (static __device__ arrays: sanctioned no-alloc workaround)
// ============================================================================
__device__ __half g_A[(size_t)NROWS * KTOT];   // 151 MB
__device__ __half g_W[(size_t)D_OUT * KTOT];   // 37.7 MB

// ============================================================================
// PTX helpers (base ISA only — harness builds for compute_103, no 'a')
// ============================================================================
__device__ __forceinline__ uint32_t smem_u32(const void* p) {
    uint32_t a;
    asm("{ .reg .u64 t; cvta.to.shared.u64 t, %1; cvt.u32.u64 %0, t; }" : "=r"(a) : "l"(p));
    return a;
}

__device__ __forceinline__ void cp16(uint32_t dst, const void* src) {
    asm volatile("cp.async.cg.shared.global [%0], [%1], 16;" :: "r"(dst), "l"(src));
}
#define CP_COMMIT() asm volatile("cp.async.commit_group;" ::: "memory")
#define CP_WAIT_1() asm volatile("cp.async.wait_group 1;" ::: "memory")

__device__ __forceinline__ void ldsm_x4(uint32_t* r, uint32_t addr) {
    asm volatile("ldmatrix.sync.aligned.m8n8.x4.shared.b16 {%0,%1,%2,%3}, [%4];"
                 : "=r"(r[0]), "=r"(r[1]), "=r"(r[2]), "=r"(r[3]) : "r"(addr));
}

__device__ __forceinline__ void mma_f16(float* c, const uint32_t* a,
                                        uint32_t b0, uint32_t b1) {
    asm volatile(
        "mma.sync.aligned.m16n8k16.row.col.f32.f16.f16.f32 "
        "{%0,%1,%2,%3}, {%4,%5,%6,%7}, {%8,%9}, {%0,%1,%2,%3};"
        : "+f"(c[0]), "+f"(c[1]), "+f"(c[2]), "+f"(c[3])
        : "r"(a[0]), "r"(a[1]), "r"(a[2]), "r"(a[3]), "r"(b0), "r"(b1));
}

// ============================================================================
// Merged prep kernel. Blocks [0, 32768): A-side (one thread per (n,d)):
//   basis block A[n][d*8+j] = B_j(x[n,d]) (exact Cox-de-Boor recursion,
//   uniform grid: all denominators are p*h -> one rcp, zero divides);
//   silu block  A[n][8192+d] = silu(x[n,d]).
// Blocks [32768, 40960): W-side (one thread per (d,o)):
//   W[o][d*8+j] = coef[d][o][j]*ssp[d][o];  W[o][8192+d] = sb[d][o].
// ============================================================================
__global__ void prep_kernel(const float* __restrict__ x, const float* __restrict__ grid,
                            const float* __restrict__ coef, const float* __restrict__ sb,
                            const float* __restrict__ ssp) {
    if (blockIdx.x < 32768u) {
        int idx = blockIdx.x * blockDim.x + threadIdx.x;   // n*1024 + d
        int d = idx & (D_IN - 1);
        int n = idx >> 10;
        float xv = x[idx];
        float gv[12];
#pragma unroll
        for (int m = 0; m < 12; m++) gv[m] = __ldg(grid + d * 12 + m);

        const float invh  = __frcp_rn(gv[1] - gv[0]);
        const float invp[3] = {invh, 0.5f * invh, (1.0f / 3.0f) * invh};

        float B[11];
#pragma unroll
        for (int m = 0; m < 11; m++)
            B[m] = (xv >= gv[m] && xv < gv[m + 1]) ? 1.0f : 0.0f;
#pragma unroll
        for (int p = 1; p <= 3; p++) {
            const float ip = invp[p - 1];
#pragma unroll
            for (int m = 0; m < 11 - p; m++) {
                float left  = (xv - gv[m]) * ip;
                float right = (gv[m + p + 1] - xv) * ip;
                B[m] = left * B[m] + right * B[m + 1];
            }
        }
        __half2 h[4];
#pragma unroll
        for (int j = 0; j < 4; j++)
            h[j] = __floats2half2_rn(B[2 * j], B[2 * j + 1]);
        *reinterpret_cast<uint4*>(g_A + (size_t)n * KTOT + d * 8) =
            *reinterpret_cast<uint4*>(h);
        float s = xv * __frcp_rn(1.0f + __expf(-xv));
        g_A[(size_t)n * KTOT + KBAS + d] = __float2half_rn(s);
    } else {
        int idx = (blockIdx.x - 32768u) * blockDim.x + threadIdx.x;  // d*2048 + o
        int o = idx & (D_OUT - 1);
        int d = idx >> 11;
        size_t doo = (size_t)d * D_OUT + o;
        float ss = ssp[doo];
        float4 c0 = *reinterpret_cast<const float4*>(coef + doo * 8);
        float4 c1 = *reinterpret_cast<const float4*>(coef + doo * 8 + 4);
        __half2 h[4];
        h[0] = __floats2half2_rn(c0.x * ss, c0.y * ss);
        h[1] = __floats2half2_rn(c0.z * ss, c0.w * ss);
        h[2] = __floats2half2_rn(c1.x * ss, c1.y * ss);
        h[3] = __floats2half2_rn(c1.z * ss, c1.w * ss);
        *reinterpret_cast<uint4*>(g_W + (size_t)o * KTOT + d * 8) =
            *reinterpret_cast<uint4*>(h);
        g_W[(size_t)o * KTOT + KBAS + d] = __float2half_rn(sb[doo]);
    }
}

// ============================================================================
// GEMM: out[8192,2048] = A @ W^T  (fp16 m16n8k16, f32 acc)
// Classic launch: 1024 CTAs of 128x128, 256 thr (8 warps 2x4, warp tile
// 64x32), 3-stage cp.async pipeline, 96KB smem -> 2 CTAs/SM (4 warps/SMSP:
// cross-CTA interleaving hides ldsm->mma latency and barrier phases).
// ============================================================================
__global__ __launch_bounds__(256, 2)
void kan_gemm_kernel(float* __restrict__ out) {
    extern __shared__ __align__(128) char smem[];
    const uint32_t sbase = smem_u32(smem);
    const int tid  = threadIdx.x;
    const int lane = tid & 31;
    const int wid  = tid >> 5;          // 0..7
    const int wm   = wid & 1;           // 2 m-bands of 64
    const int wn   = wid >> 1;          // 4 n-bands of 32
    const int n0 = blockIdx.x * BN;     // gridDim.x = 16 (fast axis -> L2 reuse)
    const int m0 = blockIdx.y * BM;

    // ---- fill: A 128 rows x 8 units + B 128 rows x 8 units (16B units) ----
    const int fr = tid >> 3;            // base row 0..31
    const int fu = tid & 7;             // unit within 128B row
    const int fsw = (fu ^ (fr & 7)) << 4;
    const __half* Asrc0 = g_A + (size_t)(m0 + fr) * KTOT + fu * 8;
    const __half* Bsrc0 = g_W + (size_t)(n0 + fr) * KTOT + fu * 8;
    auto fill = [&](int s, int k) {
        const __half* Asrc = Asrc0 + (size_t)k * BK;
        const __half* Bsrc = Bsrc0 + (size_t)k * BK;
        uint32_t sA = sbase + s * SM_STAGE + fr * 128 + fsw;
        uint32_t sB = sA + 16384;
#pragma unroll
        for (int i = 0; i < 4; i++)
            cp16(sA + i * 32 * 128, Asrc + (size_t)i * 32 * KTOT);
#pragma unroll
        for (int i = 0; i < 4; i++)
            cp16(sB + i * 32 * 128, Bsrc + (size_t)i * 32 * KTOT);
    };

    fill(0, 0); CP_COMMIT();
    fill(1, 1); CP_COMMIT();

    float acc[4][4][4];
#pragma unroll
    for (int a = 0; a < 4; a++)
#pragma unroll
        for (int j = 0; j < 4; j++)
#pragma unroll
            for (int c = 0; c < 4; c++) acc[a][j][c] = 0.0f;

    // ldmatrix addressing (x4 = one 16x16 fp16 tile)
    const int s7  = lane & 7;
    const int hi  = lane >> 4;
    const int r16 = lane & 15;
    const uint32_t rowA_off = (uint32_t)(wm * 64 + r16) * 128;
    const uint32_t rowB_off = (uint32_t)(wn * 32 + r16) * 128 + 16384;

    int s = 0;                          // stage of step k (manual mod-3)
    int sf = 2;                         // stage of step k+2
    for (int k = 0; k < NSTEPS; k++) {
        CP_WAIT_1();                    // stage s resident
        __syncthreads();                // all warps done reading retiring stage
        if (k + 2 < NSTEPS) fill(sf, k + 2);
        CP_COMMIT();                    // empty group in tail keeps count exact

        const uint32_t sA = sbase + s * SM_STAGE + rowA_off;
        const uint32_t sB = sbase + s * SM_STAGE + rowB_off;
#pragma unroll
        for (int kc = 0; kc < 4; kc++) {
            const uint32_t u = ((uint32_t)((kc * 2 + hi) ^ s7)) << 4;
            uint32_t af[4][4], bf[2][4];
#pragma unroll
            for (int a = 0; a < 4; a++) ldsm_x4(af[a], sA + a * 16 * 128 + u);
#pragma unroll
            for (int nb = 0; nb < 2; nb++) ldsm_x4(bf[nb], sB + nb * 16 * 128 + u);
#pragma unroll
            for (int a = 0; a < 4; a++)
#pragma unroll
                for (int nb = 0; nb < 2; nb++) {
                    mma_f16(acc[a][nb * 2 + 0], af[a], bf[nb][0], bf[nb][2]);
                    mma_f16(acc[a][nb * 2 + 1], af[a], bf[nb][1], bf[nb][3]);
                }
        }
        if (++s == NSTAGES) s = 0;
        if (++sf == NSTAGES) sf = 0;
    }

    // ---- epilogue: regs -> gmem ----
    const int orow0 = m0 + wm * 64 + (lane >> 2);
    const int ocol0 = n0 + wn * 32 + (lane & 3) * 2;
#pragma unroll
    for (int a = 0; a < 4; a++) {
        float* p0 = out + (size_t)(orow0 + a * 16) * D_OUT + ocol0;
        float* p1 = p0 + 8 * D_OUT;
#pragma unroll
        for (int j = 0; j < 4; j++) {
            *reinterpret_cast<float2*>(p0 + j * 8) = make_float2(acc[a][j][0], acc[a][j][1]);
            *reinterpret_cast<float2*>(p1 + j * 8) = make_float2(acc[a][j][2], acc[a][j][3]);
        }
    }
}

// ============================================================================
// Host launch (graph-capturable: kernel launches only)
// ============================================================================
extern "C" void kernel_launch(void* const* d_in, const int* in_sizes, int n_in,
                              void* d_out, int out_size) {
    const float* x    = (const float*)d_in[0];   // (4,2048,1024)
    const float* grid = (const float*)d_in[1];   // (1024,12)
    const float* coef = (const float*)d_in[2];   // (1024,2048,8)
    const float* sb   = (const float*)d_in[3];   // (1024,2048)
    const float* ssp  = (const float*)d_in[4];   // (1024,2048)
    float* out = (float*)d_out;                  // (4,2048,2048)

    prep_kernel<<<32768 + 8192, 256>>>(x, grid, coef, sb, ssp);

    cudaFuncSetAttribute(kan_gemm_kernel,
                         cudaFuncAttributeMaxDynamicSharedMemorySize, SMEM_TOTAL);
    kan_gemm_kernel<<<dim3(D_OUT / BN, NROWS / BM), 256, SMEM_TOTAL>>>(out);
}

// round 10
// speedup vs baseline: 1.1853x; 1.0016x over previous
#include <cuda_runtime.h>
#include <cuda_fp16.h>
#include <cstdint>

// ============================================================================
// Problem constants
// ============================================================================
#define D_IN   1024
#define D_OUT  2048
#define NROWS  8192               // 4 * 2048
#define KBAS   8192               // basis block: k = d*8 + j
#define KTOT   9216               // + silu block: k = 8192 + d
#define BM     128
#define BN     128
#define BK     64                 // 64 fp16 = 128B rows = SW128 atom
#define NSTEPS (KTOT / BK)        // 144
#define NSTAGES 3

// SMEM: 3 stages, each = A(16KB) + B(16KB) = 32KB -> 96KB => 2 CTAs/SM
#define SM_STAGE   32768
#define SMEM_TOTAL (NSTAGES * SM_STAGE)         // 98304

// ============================================================================
// Device scratch (static __device__ arrays: sanctioned no-alloc workaround)
// ============================================================================
__device__ __half g_A[(size_t)NROWS * KTOT];   // 151 MB
__device__ __half g_W[(size_t)D_OUT * KTOT];   // 37.7 MB

// ============================================================================
// PTX helpers (base ISA only — harness builds for compute_103, no 'a')
// ============================================================================
__device__ __forceinline__ uint32_t smem_u32(const void* p) {
    uint32_t a;
    asm("{ .reg .u64 t; cvta.to.shared.u64 t, %1; cvt.u32.u64 %0, t; }" : "=r"(a) : "l"(p));
    return a;
}

__device__ __forceinline__ void cp16(uint32_t dst, const void* src) {
    asm volatile("cp.async.cg.shared.global [%0], [%1], 16;" :: "r"(dst), "l"(src));
}
#define CP_COMMIT() asm volatile("cp.async.commit_group;" ::: "memory")
#define CP_WAIT_1() asm volatile("cp.async.wait_group 1;" ::: "memory")

__device__ __forceinline__ void ldsm_x4(uint32_t* r, uint32_t addr) {
    asm volatile("ldmatrix.sync.aligned.m8n8.x4.shared.b16 {%0,%1,%2,%3}, [%4];"
                 : "=r"(r[0]), "=r"(r[1]), "=r"(r[2]), "=r"(r[3]) : "r"(addr));
}

__device__ __forceinline__ void mma_f16(float* c, const uint32_t* a,
                                        uint32_t b0, uint32_t b1) {
    asm volatile(
        "mma.sync.aligned.m16n8k16.row.col.f32.f16.f16.f32 "
        "{%0,%1,%2,%3}, {%4,%5,%6,%7}, {%8,%9}, {%0,%1,%2,%3};"
        : "+f"(c[0]), "+f"(c[1]), "+f"(c[2]), "+f"(c[3])
        : "r"(a[0]), "r"(a[1]), "r"(a[2]), "r"(a[3]), "r"(b0), "r"(b1));
}

// ============================================================================
// Merged prep kernel. Blocks [0, 32768): A-side (one thread per (n,d)):
//   basis block A[n][d*8+j] = B_j(x[n,d]) (exact Cox-de-Boor recursion,
//   uniform grid: all denominators are p*h -> one rcp, zero divides);
//   silu block  A[n][8192+d] = silu(x[n,d]).
// Blocks [32768, 40960): W-side (one thread per (d,o)):
//   W[o][d*8+j] = coef[d][o][j]*ssp[d][o];  W[o][8192+d] = sb[d][o].
// ============================================================================
__global__ void prep_kernel(const float* __restrict__ x, const float* __restrict__ grid,
                            const float* __restrict__ coef, const float* __restrict__ sb,
                            const float* __restrict__ ssp) {
    if (blockIdx.x < 32768u) {
        int idx = blockIdx.x * blockDim.x + threadIdx.x;   // n*1024 + d
        int d = idx & (D_IN - 1);
        int n = idx >> 10;
        float xv = x[idx];
        float gv[12];
#pragma unroll
        for (int m = 0; m < 12; m++) gv[m] = __ldg(grid + d * 12 + m);

        const float invh  = __frcp_rn(gv[1] - gv[0]);
        const float invp[3] = {invh, 0.5f * invh, (1.0f / 3.0f) * invh};

        float B[11];
#pragma unroll
        for (int m = 0; m < 11; m++)
            B[m] = (xv >= gv[m] && xv < gv[m + 1]) ? 1.0f : 0.0f;
#pragma unroll
        for (int p = 1; p <= 3; p++) {
            const float ip = invp[p - 1];
#pragma unroll
            for (int m = 0; m < 11 - p; m++) {
                float left  = (xv - gv[m]) * ip;
                float right = (gv[m + p + 1] - xv) * ip;
                B[m] = left * B[m] + right * B[m + 1];
            }
        }
        __half2 h[4];
#pragma unroll
        for (int j = 0; j < 4; j++)
            h[j] = __floats2half2_rn(B[2 * j], B[2 * j + 1]);
        *reinterpret_cast<uint4*>(g_A + (size_t)n * KTOT + d * 8) =
            *reinterpret_cast<uint4*>(h);
        float s = xv * __frcp_rn(1.0f + __expf(-xv));
        g_A[(size_t)n * KTOT + KBAS + d] = __float2half_rn(s);
    } else {
        int idx = (blockIdx.x - 32768u) * blockDim.x + threadIdx.x;  // d*2048 + o
        int o = idx & (D_OUT - 1);
        int d = idx >> 11;
        size_t doo = (size_t)d * D_OUT + o;
        float ss = ssp[doo];
        float4 c0 = *reinterpret_cast<const float4*>(coef + doo * 8);
        float4 c1 = *reinterpret_cast<const float4*>(coef + doo * 8 + 4);
        __half2 h[4];
        h[0] = __floats2half2_rn(c0.x * ss, c0.y * ss);
        h[1] = __floats2half2_rn(c0.z * ss, c0.w * ss);
        h[2] = __floats2half2_rn(c1.x * ss, c1.y * ss);
        h[3] = __floats2half2_rn(c1.z * ss, c1.w * ss);
        *reinterpret_cast<uint4*>(g_W + (size_t)o * KTOT + d * 8) =
            *reinterpret_cast<uint4*>(h);
        g_W[(size_t)o * KTOT + KBAS + d] = __float2half_rn(sb[doo]);
    }
}

// ============================================================================
// GEMM: out[8192,2048] = A @ W^T  (fp16 m16n8k16, f32 acc)
// Classic launch: 1024 CTAs of 128x128, 256 thr (8 warps 2x4, warp tile
// 64x32), 3-stage cp.async pipeline, 96KB smem -> 2 CTAs/SM (4 warps/SMSP:
// cross-CTA interleaving hides ldsm->mma latency and barrier phases).
// ============================================================================
__global__ __launch_bounds__(256, 2)
void kan_gemm_kernel(float* __restrict__ out) {
    extern __shared__ __align__(128) char smem[];
    const uint32_t sbase = smem_u32(smem);
    const int tid  = threadIdx.x;
    const int lane = tid & 31;
    const int wid  = tid >> 5;          // 0..7
    const int wm   = wid & 1;           // 2 m-bands of 64
    const int wn   = wid >> 1;          // 4 n-bands of 32
    const int n0 = blockIdx.x * BN;     // gridDim.x = 16 (fast axis -> L2 reuse)
    const int m0 = blockIdx.y * BM;

    // ---- fill: A 128 rows x 8 units + B 128 rows x 8 units (16B units) ----
    const int fr = tid >> 3;            // base row 0..31
    const int fu = tid & 7;             // unit within 128B row
    const int fsw = (fu ^ (fr & 7)) << 4;
    const __half* Asrc0 = g_A + (size_t)(m0 + fr) * KTOT + fu * 8;
    const __half* Bsrc0 = g_W + (size_t)(n0 + fr) * KTOT + fu * 8;
    auto fill = [&](int s, int k) {
        const __half* Asrc = Asrc0 + (size_t)k * BK;
        const __half* Bsrc = Bsrc0 + (size_t)k * BK;
        uint32_t sA = sbase + s * SM_STAGE + fr * 128 + fsw;
        uint32_t sB = sA + 16384;
#pragma unroll
        for (int i = 0; i < 4; i++)
            cp16(sA + i * 32 * 128, Asrc + (size_t)i * 32 * KTOT);
#pragma unroll
        for (int i = 0; i < 4; i++)
            cp16(sB + i * 32 * 128, Bsrc + (size_t)i * 32 * KTOT);
    };

    fill(0, 0); CP_COMMIT();
    fill(1, 1); CP_COMMIT();

    float acc[4][4][4];
#pragma unroll
    for (int a = 0; a < 4; a++)
#pragma unroll
        for (int j = 0; j < 4; j++)
#pragma unroll
            for (int c = 0; c < 4; c++) acc[a][j][c] = 0.0f;

    // ldmatrix addressing (x4 = one 16x16 fp16 tile)
    const int s7  = lane & 7;
    const int hi  = lane >> 4;
    const int r16 = lane & 15;
    const uint32_t rowA_off = (uint32_t)(wm * 64 + r16) * 128;
    const uint32_t rowB_off = (uint32_t)(wn * 32 + r16) * 128 + 16384;

    int s = 0;                          // stage of step k (manual mod-3)
    int sf = 2;                         // stage of step k+2
    for (int k = 0; k < NSTEPS; k++) {
        CP_WAIT_1();                    // stage s resident
        __syncthreads();                // all warps done reading retiring stage
        if (k + 2 < NSTEPS) fill(sf, k + 2);
        CP_COMMIT();                    // empty group in tail keeps count exact

        const uint32_t sA = sbase + s * SM_STAGE + rowA_off;
        const uint32_t sB = sbase + s * SM_STAGE + rowB_off;
#pragma unroll
        for (int kc = 0; kc < 4; kc++) {
            const uint32_t u = ((uint32_t)((kc * 2 + hi) ^ s7)) << 4;
            uint32_t af[4][4], bf[2][4];
#pragma unroll
            for (int a = 0; a < 4; a++) ldsm_x4(af[a], sA + a * 16 * 128 + u);
#pragma unroll
            for (int nb = 0; nb < 2; nb++) ldsm_x4(bf[nb], sB + nb * 16 * 128 + u);
#pragma unroll
            for (int a = 0; a < 4; a++)
#pragma unroll
                for (int nb = 0; nb < 2; nb++) {
                    mma_f16(acc[a][nb * 2 + 0], af[a], bf[nb][0], bf[nb][2]);
                    mma_f16(acc[a][nb * 2 + 1], af[a], bf[nb][1], bf[nb][3]);
                }
        }
        if (++s == NSTAGES) s = 0;
        if (++sf == NSTAGES) sf = 0;
    }

    // ---- epilogue: regs -> gmem ----
    const int orow0 = m0 + wm * 64 + (lane >> 2);
    const int ocol0 = n0 + wn * 32 + (lane & 3) * 2;
#pragma unroll
    for (int a = 0; a < 4; a++) {
        float* p0 = out + (size_t)(orow0 + a * 16) * D_OUT + ocol0;
        float* p1 = p0 + 8 * D_OUT;
#pragma unroll
        for (int j = 0; j < 4; j++) {
            *reinterpret_cast<float2*>(p0 + j * 8) = make_float2(acc[a][j][0], acc[a][j][1]);
            *reinterpret_cast<float2*>(p1 + j * 8) = make_float2(acc[a][j][2], acc[a][j][3]);
        }
    }
}

// ============================================================================
// Host launch (graph-capturable: kernel launches only)
// ============================================================================
extern "C" void kernel_launch(void* const* d_in, const int* in_sizes, int n_in,
                              void* d_out, int out_size) {
    const float* x    = (const float*)d_in[0];   // (4,2048,1024)
    const float* grid = (const float*)d_in[1];   // (1024,12)
    const float* coef = (const float*)d_in[2];   // (1024,2048,8)
    const float* sb   = (const float*)d_in[3];   // (1024,2048)
    const float* ssp  = (const float*)d_in[4];   // (1024,2048)
    float* out = (float*)d_out;                  // (4,2048,2048)

    prep_kernel<<<32768 + 8192, 256>>>(x, grid, coef, sb, ssp);

    cudaFuncSetAttribute(kan_gemm_kernel,
                         cudaFuncAttributeMaxDynamicSharedMemorySize, SMEM_TOTAL);
    kan_gemm_kernel<<<dim3(D_OUT / BN, NROWS / BM), 256, SMEM_TOTAL>>>(out);
}